// round 10
// baseline (speedup 1.0000x reference)
#include <cuda_runtime.h>
#include <cuda_bf16.h>
#include <math.h>

// ---------------- scratch (static device globals) ------------------------------
__device__ float g_h [16777216];                 // LN1 output          (B,64,N)
__device__ float g_g [16777216];                 // dwconv output       (B,64,N)
__device__ __nv_bfloat162 g_qh[8388608];         // q bf16 pairs        (B,32,N)
__device__ __nv_bfloat162 g_kh[8388608];         // k bf16 pairs        (B,32,N)
__device__ unsigned long long g_vp[8388608];     // v f32 pairs         (B,32,N)
__device__ float g_xn[16777216];                 // x + attn_proj       (B,64,N)
__device__ float g_ln[16777216];                 // LN2 out             (B,64,N)
__device__ float g_m [67108864];                 // mlp_in output       (B,256,N)
__device__ float g_gt[16777216];                 // gated+BN            (B,64,N)
__device__ float g_sq[256];
__device__ float g_sk[256];
__device__ float g_sv[256];
__device__ float g_gram[2048];
__device__ float g_W[2048];                      // softmax weights, 1/||v|| folded
__device__ float g_M[16384];                     // per-batch proj*attn (4 x 64 x 64)

// ---------------- f32x2 helpers -------------------------------------------------
__device__ __forceinline__ unsigned long long pk2(float a, float b) {
    unsigned long long r;
    asm("mov.b64 %0, {%1, %2};" : "=l"(r) : "f"(a), "f"(b));
    return r;
}
__device__ __forceinline__ void fma2(unsigned long long& acc, unsigned long long w,
                                     unsigned long long v) {
    asm("fma.rn.f32x2 %0, %1, %2, %0;" : "+l"(acc) : "l"(w), "l"(v));
}
__device__ __forceinline__ void unpk2(unsigned long long a, float& lo, float& hi) {
    asm("mov.b64 {%0, %1}, %2;" : "=f"(lo), "=f"(hi) : "l"(a));
}
__device__ __forceinline__ float hadd2(unsigned long long a) {
    float lo, hi; unpk2(a, lo, hi); return lo + hi;
}

// ---------------- K0: zero accumulators -----------------------------------------
__global__ void k_zero() {
    int t = blockIdx.x * 256 + threadIdx.x;
    if (t < 256) { g_sq[t] = 0.f; g_sk[t] = 0.f; g_sv[t] = 0.f; }
    if (t < 2048) g_gram[t] = 0.f;
}

// ---------------- K1: LayerNorm over C=64 per pixel -----------------------------
__global__ void __launch_bounds__(256) k_ln1(const float* __restrict__ x,
                                             const float* __restrict__ w,
                                             const float* __restrict__ bia) {
    int p = blockIdx.x * 256 + threadIdx.x;
    int bb = p >> 16, pix = p & 65535;
    size_t base = ((size_t)bb << 22) + pix;
    float v[64]; float mu = 0.f;
    #pragma unroll
    for (int c = 0; c < 64; c++) { v[c] = x[base + ((size_t)c << 16)]; mu += v[c]; }
    mu *= 0.015625f;
    float var = 0.f;
    #pragma unroll
    for (int c = 0; c < 64; c++) { float d = v[c] - mu; var += d * d; }
    var *= 0.015625f;
    float rs = rsqrtf(var + 1e-5f);
    #pragma unroll
    for (int c = 0; c < 64; c++)
        g_h[base + ((size_t)c << 16)] = (v[c] - mu) * rs * w[c] + bia[c];
}

// ---------------- K2: 3x3 depthwise conv, zero pad ------------------------------
__global__ void __launch_bounds__(256) k_dw(const float* __restrict__ w) {
    int idx = blockIdx.x * 256 + threadIdx.x;
    int pix = idx & 65535; int bc = idx >> 16; int c = bc & 63;
    int r = pix >> 8, cl = pix & 255;
    const float* pl = g_h + ((size_t)bc << 16);
    const float* wt = w + c * 9;
    float acc = 0.f;
    #pragma unroll
    for (int dy = 0; dy < 3; dy++) {
        int rr = r + dy - 1;
        if ((unsigned)rr > 255u) continue;
        #pragma unroll
        for (int dx = 0; dx < 3; dx++) {
            int cc = cl + dx - 1;
            if ((unsigned)cc > 255u) continue;
            acc += wt[dy * 3 + dx] * pl[(rr << 8) + cc];
        }
    }
    g_g[idx] = acc;
}

// ---------------- K3: tiled q/k/v GEMM ------------------------------------------
// block: 128 px tile, all 192 outputs. smem: sp[64][132] input + wT[64][196].
// thread (to=tid>>4, tp=tid&15): 6 output-pairs x 8 px (px = tp + 16j).
#define QKV_SMEM ((64 * 132 + 64 * 196) * 4)
__global__ void __launch_bounds__(256) k_qkv_t(const float* __restrict__ qw,
                                               const float* __restrict__ kw,
                                               const float* __restrict__ vw) {
    extern __shared__ __align__(16) float s[];
    float* sp = s;                 // 64*132
    float* wT = s + 64 * 132;      // 64*196
    int tid = threadIdx.x;
    for (int i = tid; i < 4096; i += 256) {
        int o = i >> 6, k = i & 63;
        wT[k * 196 + o]       = qw[i];
        wT[k * 196 + 64 + o]  = kw[i];
        wT[k * 196 + 128 + o] = vw[i];
    }
    int bb = blockIdx.y;
    int px0 = blockIdx.x << 7;
    size_t gb = ((size_t)bb << 22) + px0;
    for (int i = tid; i < 2048; i += 256) {
        int ch = i >> 5, seg = i & 31;
        float4 v4 = *(const float4*)(g_g + gb + ((size_t)ch << 16) + seg * 4);
        *(float4*)(sp + ch * 132 + seg * 4) = v4;
    }
    __syncthreads();

    int to = tid >> 4, tp = tid & 15;
    unsigned long long acc[6][8];
    #pragma unroll
    for (int u = 0; u < 6; u++)
        #pragma unroll
        for (int j = 0; j < 8; j++) acc[u][j] = 0ull;

    #pragma unroll 2
    for (int k = 0; k < 64; k++) {
        const ulonglong2* w2 = (const ulonglong2*)(wT + k * 196 + to * 12);
        ulonglong2 p01 = w2[0], p23 = w2[1], p45 = w2[2];
        const float* prow = sp + k * 132 + tp;
        #pragma unroll
        for (int j = 0; j < 8; j++) {
            float pv = prow[16 * j];
            unsigned long long pp = pk2(pv, pv);
            fma2(acc[0][j], p01.x, pp); fma2(acc[1][j], p01.y, pp);
            fma2(acc[2][j], p23.x, pp); fma2(acc[3][j], p23.y, pp);
            fma2(acc[4][j], p45.x, pp); fma2(acc[5][j], p45.y, pp);
        }
    }
    // stores: op = to*6+u  (op<32: q pair, <64: k pair, else v pair)
    size_t pb = ((size_t)bb << 21) + px0 + tp;
    #pragma unroll
    for (int u = 0; u < 6; u++) {
        int op = to * 6 + u;
        if (op < 32) {
            #pragma unroll
            for (int j = 0; j < 8; j++) {
                float lo, hi; unpk2(acc[u][j], lo, hi);
                g_qh[pb + ((size_t)op << 16) + 16 * j] = __floats2bfloat162_rn(lo, hi);
            }
        } else if (op < 64) {
            #pragma unroll
            for (int j = 0; j < 8; j++) {
                float lo, hi; unpk2(acc[u][j], lo, hi);
                g_kh[pb + ((size_t)(op - 32) << 16) + 16 * j] = __floats2bfloat162_rn(lo, hi);
            }
        } else {
            #pragma unroll
            for (int j = 0; j < 8; j++)
                g_vp[pb + ((size_t)(op - 64) << 16) + 16 * j] = acc[u][j];
        }
    }
}

// ---------------- K4: Gram + sum-of-squares reduction ---------------------------
__global__ void __launch_bounds__(256) k_stats() {
    int tid = threadIdx.x;
    int chunk = blockIdx.x, hh = blockIdx.y, bb = blockIdx.z;
    float aq[8] = {0}, ak[8] = {0}, av[8] = {0}, G[64] = {0};
    size_t hb2 = ((size_t)bb << 21);
    for (int it = 0; it < 32; it++) {
        int p = chunk * 8192 + it * 256 + tid;
        float qv[8], kv[8], vv[8];
        #pragma unroll
        for (int jp = 0; jp < 4; jp++) {
            size_t idx = hb2 + ((size_t)(hh * 4 + jp) << 16) + p;
            __nv_bfloat162 qp = g_qh[idx];
            __nv_bfloat162 kp = g_kh[idx];
            qv[2*jp] = __bfloat162float(qp.x); qv[2*jp+1] = __bfloat162float(qp.y);
            kv[2*jp] = __bfloat162float(kp.x); kv[2*jp+1] = __bfloat162float(kp.y);
            unpk2(g_vp[idx], vv[2*jp], vv[2*jp+1]);
        }
        #pragma unroll
        for (int j = 0; j < 8; j++) {
            aq[j] += qv[j]*qv[j]; ak[j] += kv[j]*kv[j]; av[j] += vv[j]*vv[j];
        }
        #pragma unroll
        for (int d = 0; d < 8; d++)
            #pragma unroll
            for (int e = 0; e < 8; e++) G[d*8+e] += qv[d]*kv[e];
    }
    #pragma unroll
    for (int off = 16; off; off >>= 1) {
        #pragma unroll
        for (int j = 0; j < 8; j++) {
            aq[j] += __shfl_xor_sync(~0u, aq[j], off);
            ak[j] += __shfl_xor_sync(~0u, ak[j], off);
            av[j] += __shfl_xor_sync(~0u, av[j], off);
        }
        #pragma unroll
        for (int j = 0; j < 64; j++) G[j] += __shfl_xor_sync(~0u, G[j], off);
    }
    __shared__ float red[88];
    if (tid < 88) red[tid] = 0.f;
    __syncthreads();
    if ((tid & 31) == 0) {
        #pragma unroll
        for (int j = 0; j < 8; j++) {
            atomicAdd(&red[j], aq[j]); atomicAdd(&red[8+j], ak[j]); atomicAdd(&red[16+j], av[j]);
        }
        #pragma unroll
        for (int j = 0; j < 64; j++) atomicAdd(&red[24+j], G[j]);
    }
    __syncthreads();
    if (tid < 8)        atomicAdd(&g_sq[bb*64 + hh*8 + tid],        red[tid]);
    else if (tid < 16)  atomicAdd(&g_sk[bb*64 + hh*8 + tid - 8],    red[tid]);
    else if (tid < 24)  atomicAdd(&g_sv[bb*64 + hh*8 + tid - 16],   red[tid]);
    else if (tid < 88)  atomicAdd(&g_gram[(bb*8 + hh)*64 + tid-24], red[tid]);
}

// ---------------- K5: softmax weights + combined M = proj*blockdiag(W) ----------
__global__ void k_attmix(const float* __restrict__ projw) {
    int t = threadIdx.x;
    {   // phase 1: softmax weights (t = b*64 + h*8 + d)
        int d = t & 7; int bh = t >> 3; int bb = bh >> 3; int hh = bh & 7;
        float nq = fmaxf(sqrtf(g_sq[bb*64 + hh*8 + d]), 1e-12f);
        const float scale = 0.35355339059327373f;
        float row[8]; float mx = -1e30f;
        #pragma unroll
        for (int e = 0; e < 8; e++) {
            float ne = fmaxf(sqrtf(g_sk[bb*64 + hh*8 + e]), 1e-12f);
            row[e] = g_gram[bh*64 + d*8 + e] * scale / (nq * ne);
            mx = fmaxf(mx, row[e]);
        }
        float sum = 0.f;
        #pragma unroll
        for (int e = 0; e < 8; e++) { row[e] = expf(row[e] - mx); sum += row[e]; }
        float inv = 1.f / sum;
        #pragma unroll
        for (int e = 0; e < 8; e++) {
            float nv = fmaxf(sqrtf(g_sv[bb*64 + hh*8 + e]), 1e-12f);
            g_W[bh*64 + d*8 + e] = row[e] * inv / nv;
        }
    }
    __syncthreads();
    {   // phase 2: M_b = proj * blockdiag(W)  (t = b*64 + oc)
        int bb = t >> 6, oc = t & 63;
        for (int c = 0; c < 64; c++) {
            int h = c >> 3, e = c & 7;
            float a = 0.f;
            #pragma unroll
            for (int d = 0; d < 8; d++)
                a += projw[oc*64 + (h<<3) + d] * g_W[((bb<<3) + h)*64 + (d<<3) + e];
            g_M[bb*4096 + oc*64 + c] = a;
        }
    }
}

// ---------------- K6a: attn+proj + residual + LN2 (P=1) -------------------------
__global__ void __launch_bounds__(256) k_fuse1(const float* __restrict__ x,
                                               const float* __restrict__ ln2w,
                                               const float* __restrict__ ln2b) {
    __shared__ __align__(16) float sM[4096];
    __shared__ float slw[64], slb[64];
    int tid = threadIdx.x; int bb = blockIdx.y;
    for (int i = tid; i < 4096; i += 256) sM[i] = g_M[bb*4096 + i];
    if (tid < 64) { slw[tid] = ln2w[tid]; slb[tid] = ln2b[tid]; }
    __syncthreads();
    int pix = blockIdx.x * 256 + tid;
    size_t base = ((size_t)bb << 22) + pix;
    size_t pbase = ((size_t)bb << 21) + pix;
    unsigned long long vp[32];
    #pragma unroll
    for (int c = 0; c < 32; c++) vp[c] = g_vp[pbase + ((size_t)c << 16)];
    float y[64]; float mu = 0.f;
    #pragma unroll
    for (int oc = 0; oc < 64; oc++) {
        const ulonglong2* row = (const ulonglong2*)(sM + (oc << 6));
        unsigned long long acc = 0ull;
        #pragma unroll
        for (int c4 = 0; c4 < 16; c4++) {
            ulonglong2 w2 = row[c4];
            fma2(acc, w2.x, vp[2*c4]); fma2(acc, w2.y, vp[2*c4+1]);
        }
        y[oc] = hadd2(acc) + x[base + ((size_t)oc << 16)];
        mu += y[oc];
    }
    mu *= 0.015625f;
    float var = 0.f;
    #pragma unroll
    for (int c = 0; c < 64; c++) {
        float d = y[c] - mu; var += d * d;
        g_xn[base + ((size_t)c << 16)] = y[c];
    }
    float rs = rsqrtf(var * 0.015625f + 1e-5f);
    #pragma unroll
    for (int c = 0; c < 64; c++)
        g_ln[base + ((size_t)c << 16)] = (y[c] - mu) * rs * slw[c] + slb[c];
}

// ---------------- K6b: tiled mlp_in GEMM (64 -> 256) ----------------------------
// block: 64 px tile. smem: sp[64][68] + wT[64][260].
// thread (to=tid>>4, tp=tid&15): 8 output-pairs x 4 px (px = tp + 16j).
#define F2_SMEM ((64 * 68 + 64 * 260) * 4)
__global__ void __launch_bounds__(256) k_fuse2_t(const float* __restrict__ mlpw) {
    extern __shared__ __align__(16) float s2[];
    float* sp = s2;               // 64*68
    float* wT = s2 + 64 * 68;     // 64*260
    int tid = threadIdx.x;
    for (int i = tid; i < 16384; i += 256) {
        int o = i >> 6, k = i & 63;
        wT[k * 260 + o] = mlpw[i];
    }
    int bb = blockIdx.y;
    int px0 = blockIdx.x << 6;
    size_t gb = ((size_t)bb << 22) + px0;
    for (int i = tid; i < 1024; i += 256) {
        int ch = i >> 4, seg = i & 15;
        float4 v4 = *(const float4*)(g_ln + gb + ((size_t)ch << 16) + seg * 4);
        *(float4*)(sp + ch * 68 + seg * 4) = v4;
    }
    __syncthreads();

    int to = tid >> 4, tp = tid & 15;
    unsigned long long acc[8][4];
    #pragma unroll
    for (int u = 0; u < 8; u++)
        #pragma unroll
        for (int j = 0; j < 4; j++) acc[u][j] = 0ull;

    #pragma unroll 2
    for (int k = 0; k < 64; k++) {
        const ulonglong2* w2 = (const ulonglong2*)(wT + k * 260 + to * 16);
        ulonglong2 p01 = w2[0], p23 = w2[1], p45 = w2[2], p67 = w2[3];
        const float* prow = sp + k * 68 + tp;
        #pragma unroll
        for (int j = 0; j < 4; j++) {
            float pv = prow[16 * j];
            unsigned long long pp = pk2(pv, pv);
            fma2(acc[0][j], p01.x, pp); fma2(acc[1][j], p01.y, pp);
            fma2(acc[2][j], p23.x, pp); fma2(acc[3][j], p23.y, pp);
            fma2(acc[4][j], p45.x, pp); fma2(acc[5][j], p45.y, pp);
            fma2(acc[6][j], p67.x, pp); fma2(acc[7][j], p67.y, pp);
        }
    }
    size_t mb = ((size_t)bb << 24) + px0 + tp;
    #pragma unroll
    for (int u = 0; u < 8; u++) {
        int o = (to * 8 + u) * 2;
        #pragma unroll
        for (int j = 0; j < 4; j++) {
            float lo, hi; unpk2(acc[u][j], lo, hi);
            g_m[mb + ((size_t)o << 16) + 16 * j]       = lo;
            g_m[mb + ((size_t)(o + 1) << 16) + 16 * j] = hi;
        }
    }
}

// ---------------- K7a: grouped 3x3 (reflect pad) + SiLU gate + BN ---------------
__global__ void __launch_bounds__(256) k_mlpdw(const float* __restrict__ dww,
                                               const float* __restrict__ bng,
                                               const float* __restrict__ bnb,
                                               const float* __restrict__ bnm,
                                               const float* __restrict__ bnv) {
    __shared__ float sw[4608];
    __shared__ float ssc[64], ssh[64];
    int tid = threadIdx.x;
    for (int i = tid; i < 4608; i += 256) sw[i] = dww[i];
    if (tid < 64) {
        float sc = bng[tid] * rsqrtf(bnv[tid] + 1e-5f);
        ssc[tid] = sc; ssh[tid] = bnb[tid] - bnm[tid] * sc;
    }
    __syncthreads();
    int t = blockIdx.x * 256 + tid;
    int p4 = t << 2;
    int bb = p4 >> 16, pix = p4 & 65535;
    int r = pix >> 8, c0 = pix & 255;
    int rm = r ? r - 1 : 1;
    int rp = (r == 255) ? 254 : r + 1;
    int ro0 = rm << 8, ro1 = r << 8, ro2 = rp << 8;
    int cols[6];
    #pragma unroll
    for (int k = 0; k < 6; k++) {
        int cx = c0 + k - 1;
        cols[k] = cx < 0 ? -cx : (cx > 255 ? 510 - cx : cx);
    }
    const float* mb = g_m + ((size_t)bb << 24);
    size_t obase = ((size_t)bb << 22) + pix;
    for (int cc = 0; cc < 32; cc++) {
        float A[4]={0,0,0,0}, Bx[4]={0,0,0,0}, Cx[4]={0,0,0,0}, Dx[4]={0,0,0,0};
        const float* w1a = sw + (2*cc)    * 36;
        const float* w1b = sw + (2*cc+1)  * 36;
        const float* w2a = sw + (64+2*cc) * 36;
        const float* w2b = sw + (65+2*cc) * 36;
        #pragma unroll
        for (int i = 0; i < 4; i++) {
            const float* p1 = mb + ((size_t)(4*cc + i)       << 16);
            const float* p2 = mb + ((size_t)(128 + 4*cc + i) << 16);
            float v1[18], v2[18];
            #pragma unroll
            for (int k = 0; k < 6; k++) {
                v1[k]    = p1[ro0 + cols[k]]; v1[6+k]  = p1[ro1 + cols[k]]; v1[12+k] = p1[ro2 + cols[k]];
                v2[k]    = p2[ro0 + cols[k]]; v2[6+k]  = p2[ro1 + cols[k]]; v2[12+k] = p2[ro2 + cols[k]];
            }
            #pragma unroll
            for (int ky = 0; ky < 3; ky++)
                #pragma unroll
                for (int kx = 0; kx < 3; kx++) {
                    float wa = w1a[i*9+ky*3+kx], wb = w1b[i*9+ky*3+kx];
                    float wc = w2a[i*9+ky*3+kx], wd = w2b[i*9+ky*3+kx];
                    #pragma unroll
                    for (int j = 0; j < 4; j++) {
                        float u1 = v1[ky*6 + j + kx], u2 = v2[ky*6 + j + kx];
                        A[j]  += wa * u1; Bx[j] += wb * u1;
                        Cx[j] += wc * u2; Dx[j] += wd * u2;
                    }
                }
        }
        int c1 = 2*cc, c2 = 2*cc + 1;
        float r1[4], r2[4];
        #pragma unroll
        for (int j = 0; j < 4; j++) {
            float s1 = A[j]  / (1.f + expf(-A[j]))  * Cx[j];
            float s2 = Bx[j] / (1.f + expf(-Bx[j])) * Dx[j];
            r1[j] = s1 * ssc[c1] + ssh[c1];
            r2[j] = s2 * ssc[c2] + ssh[c2];
        }
        *(float4*)(&g_gt[obase + ((size_t)c1 << 16)]) = make_float4(r1[0], r1[1], r1[2], r1[3]);
        *(float4*)(&g_gt[obase + ((size_t)c2 << 16)]) = make_float4(r2[0], r2[1], r2[2], r2[3]);
    }
}

// ---------------- K7b: out_w 1x1 + final residual, P=2 --------------------------
__global__ void __launch_bounds__(256) k_out(const float* __restrict__ ow,
                                             float* __restrict__ out) {
    __shared__ __align__(16) float s[4096];
    int tid = threadIdx.x;
    for (int i = tid; i < 4096; i += 256) s[i] = ow[i];
    __syncthreads();
    int px = blockIdx.x * 512 + tid; int bb = blockIdx.y;
    size_t base = ((size_t)bb << 22) + px;
    unsigned long long in0[32], in1[32];
    #pragma unroll
    for (int c = 0; c < 32; c++) {
        in0[c] = pk2(g_gt[base + ((size_t)(2*c) << 16)],
                     g_gt[base + ((size_t)(2*c+1) << 16)]);
        in1[c] = pk2(g_gt[base + 256 + ((size_t)(2*c) << 16)],
                     g_gt[base + 256 + ((size_t)(2*c+1) << 16)]);
    }
    #pragma unroll 2
    for (int oc = 0; oc < 64; oc++) {
        const ulonglong2* row = (const ulonglong2*)(s + (oc << 6));
        unsigned long long a0 = 0ull, a1 = 0ull;
        #pragma unroll
        for (int c4 = 0; c4 < 16; c4++) {
            ulonglong2 w2 = row[c4];
            fma2(a0, w2.x, in0[2*c4]); fma2(a0, w2.y, in0[2*c4+1]);
            fma2(a1, w2.x, in1[2*c4]); fma2(a1, w2.y, in1[2*c4+1]);
        }
        size_t oi = base + ((size_t)oc << 16);
        out[oi]       = g_xn[oi]       + hadd2(a0);
        out[oi + 256] = g_xn[oi + 256] + hadd2(a1);
    }
}

// ---------------- launch ---------------------------------------------------------
extern "C" void kernel_launch(void* const* d_in, const int* in_sizes, int n_in,
                              void* d_out, int out_size) {
    const float* x     = (const float*)d_in[0];
    const float* ln1w  = (const float*)d_in[1];
    const float* ln1b  = (const float*)d_in[2];
    const float* ln2w  = (const float*)d_in[3];
    const float* ln2b  = (const float*)d_in[4];
    const float* dww   = (const float*)d_in[5];
    const float* qw    = (const float*)d_in[6];
    const float* kw    = (const float*)d_in[7];
    const float* vw    = (const float*)d_in[8];
    const float* projw = (const float*)d_in[9];
    const float* mlpw  = (const float*)d_in[10];
    const float* mdww  = (const float*)d_in[11];
    const float* bng   = (const float*)d_in[12];
    const float* bnb   = (const float*)d_in[13];
    const float* bnm   = (const float*)d_in[14];
    const float* bnv   = (const float*)d_in[15];
    const float* ow    = (const float*)d_in[16];
    float* out = (float*)d_out;

    cudaFuncSetAttribute(k_qkv_t,  cudaFuncAttributeMaxDynamicSharedMemorySize, QKV_SMEM);
    cudaFuncSetAttribute(k_fuse2_t, cudaFuncAttributeMaxDynamicSharedMemorySize, F2_SMEM);

    k_zero<<<8, 256>>>();
    k_ln1<<<1024, 256>>>(x, ln1w, ln1b);
    k_dw<<<65536, 256>>>(dww);
    dim3 gq(512, 4);
    k_qkv_t<<<gq, 256, QKV_SMEM>>>(qw, kw, vw);
    dim3 gs(8, 8, 4);
    k_stats<<<gs, 256>>>();
    k_attmix<<<1, 256>>>(projw);
    dim3 gf1(256, 4);
    k_fuse1<<<gf1, 256>>>(x, ln2w, ln2b);
    dim3 gf2(1024, 4);
    k_fuse2_t<<<gf2, 256, F2_SMEM>>>(mlpw);
    k_mlpdw<<<256, 256>>>(mdww, bng, bnb, bnm, bnv);
    dim3 go(128, 4);
    k_out<<<go, 256>>>(ow, out);
}